// round 2
// baseline (speedup 1.0000x reference)
#include <cuda_runtime.h>
#include <math.h>

#define Bc 8
#define Tc 256
#define Uc 101
#define Vc 512
#define NEGF (-1e30f)

// Scratch (no cudaMalloc allowed): blankp (B,T,U), emit (B,T,U-1)
__device__ float g_blank[Bc * Tc * Uc];
__device__ float g_emit[Bc * Tc * (Uc - 1)];

// ---------------------------------------------------------------------------
// Pass 1: per-(b,t,u) log-softmax reduction over V=512.
// One warp per row. 4 x float4 per lane, coalesced. Writes:
//   blankp[b,t,u] = acts[b,t,u,0]      - lse
//   emit  [b,t,u] = acts[b,t,u,lab(u)] - lse   (u < U-1)
// Label element is extracted from the registers already holding the row
// (lane (lab/4)%32, slot 4*(lab/128)+lab%4) via shuffle -- no extra LDG.
// ---------------------------------------------------------------------------
__global__ __launch_bounds__(256) void lse_kernel(const float* __restrict__ acts,
                                                  const int* __restrict__ labels) {
    const int gwarp = blockIdx.x * 8 + (threadIdx.x >> 5);   // row id, grid sized exactly
    const int lane  = threadIdx.x & 31;

    const int u = gwarp % Uc;
    const int b = gwarp / (Tc * Uc);

    const float4* row = reinterpret_cast<const float4*>(acts) + (size_t)gwarp * (Vc / 4);

    // load label early (uniform per warp, tiny, L2-resident after first pass)
    int lab = 0;
    if (u < Uc - 1) lab = __ldg(labels + b * (Uc - 1) + u);

    float v[16];
    float mx = -INFINITY;
#pragma unroll
    for (int j = 0; j < 4; j++) {
        float4 f = row[lane + 32 * j];
        v[4 * j + 0] = f.x; v[4 * j + 1] = f.y;
        v[4 * j + 2] = f.z; v[4 * j + 3] = f.w;
        mx = fmaxf(mx, fmaxf(fmaxf(f.x, f.y), fmaxf(f.z, f.w)));
    }

    // pull the label element out of the warp's registers before reductions
    const int src_lane = (lab >> 2) & 31;            // (lab/4) % 32
    const int src_slot = 4 * (lab >> 7) + (lab & 3); // 4*(lab/128) + lab%4
    float cand = v[src_slot & 15];
    // slot is data-dependent per warp but uniform across lanes -> select then shuffle
    float sel;
    switch (src_slot) {
        case 0: sel = v[0]; break;  case 1: sel = v[1]; break;
        case 2: sel = v[2]; break;  case 3: sel = v[3]; break;
        case 4: sel = v[4]; break;  case 5: sel = v[5]; break;
        case 6: sel = v[6]; break;  case 7: sel = v[7]; break;
        case 8: sel = v[8]; break;  case 9: sel = v[9]; break;
        case 10: sel = v[10]; break; case 11: sel = v[11]; break;
        case 12: sel = v[12]; break; case 13: sel = v[13]; break;
        case 14: sel = v[14]; break; default: sel = v[15]; break;
    }
    (void)cand;
    const float labval = __shfl_sync(0xffffffffu, sel, src_lane);

#pragma unroll
    for (int o = 16; o; o >>= 1) mx = fmaxf(mx, __shfl_xor_sync(0xffffffffu, mx, o));

    float s = 0.f;
#pragma unroll
    for (int k = 0; k < 16; k++) s += __expf(v[k] - mx);
#pragma unroll
    for (int o = 16; o; o >>= 1) s += __shfl_xor_sync(0xffffffffu, s, o);

    const float lse = mx + __logf(s);

    if (lane == 0) {
        g_blank[gwarp] = v[0] - lse;                       // element 0 lives in lane 0 slot 0
        if (u < Uc - 1) {
            const int t = (gwarp / Uc) % Tc;
            g_emit[(b * Tc + t) * (Uc - 1) + u] = labval - lse;
        }
    }
}

// ---------------------------------------------------------------------------
// Pass 2: RNNT alpha DP, anti-diagonal wavefront.
// One block per batch. All 256 threads stage blank/emit into SMEM (~205 KB),
// then warp 0 runs the wavefront with the diagonal held in registers
// (4 u-cells per lane, shfl_up across the lane boundary). No barriers in loop.
//   alpha[t,u] = logaddexp(alpha[t-1,u] + blank[t-1,u],
//                          alpha[t,u-1] + emit[t,u-1]),  alpha[0,0] = 0
//   loss[b] = -(alpha[tlen-1, ulen] + blank[tlen-1, ulen])
// ---------------------------------------------------------------------------
__global__ __launch_bounds__(256) void dp_kernel(const int* __restrict__ act_lens,
                                                 const int* __restrict__ label_lens,
                                                 float* __restrict__ out) {
    extern __shared__ float smem[];
    float* sB = smem;                    // Tc*Uc
    float* sE = smem + Tc * Uc;          // Tc*(Uc-1)

    const int b = blockIdx.x;
    const float* gb = g_blank + (size_t)b * Tc * Uc;
    const float* ge = g_emit + (size_t)b * Tc * (Uc - 1);

    for (int i = threadIdx.x; i < Tc * Uc; i += blockDim.x) sB[i] = gb[i];
    for (int i = threadIdx.x; i < Tc * (Uc - 1); i += blockDim.x) sE[i] = ge[i];
    __syncthreads();

    if (threadIdx.x >= 32) return;
    const int lane = threadIdx.x;
    const int tlen = act_lens[b];
    const int ulen = label_lens[b];

    float p[4] = {NEGF, NEGF, NEGF, NEGF};   // diagonal values: lane covers u = 4*lane + k

    const int D = Tc + Uc - 1;               // 356 diagonals
    for (int d = 0; d < D; d++) {
        const float up = __shfl_up_sync(0xffffffffu, p[3], 1);   // prev[u-1] across lane boundary
        float nv[4];
#pragma unroll
        for (int k = 0; k < 4; k++) {
            const int u = 4 * lane + k;
            const int t = d - u;
            float val = NEGF;
            if (u < Uc && t >= 0 && t < Tc) {
                if (t == 0 && u == 0) {
                    val = 0.f;
                } else {
                    const float a   = (t > 0) ? p[k] + sB[(t - 1) * Uc + u] : NEGF;
                    const float pm1 = (k == 0) ? up : p[k - 1];
                    const float bb  = (u > 0) ? pm1 + sE[t * (Uc - 1) + (u - 1)] : NEGF;
                    const float hi = fmaxf(a, bb);
                    const float lo = fminf(a, bb);
                    val = hi + log1pf(__expf(lo - hi));
                }
                if (t == tlen - 1 && u == ulen)
                    out[b] = -(val + sB[(tlen - 1) * Uc + ulen]);
            }
            nv[k] = val;
        }
#pragma unroll
        for (int k = 0; k < 4; k++) p[k] = nv[k];
    }
}

extern "C" void kernel_launch(void* const* d_in, const int* in_sizes, int n_in,
                              void* d_out, int out_size) {
    const float* acts       = (const float*)d_in[0];
    const int*   labels     = (const int*)d_in[1];
    const int*   act_lens   = (const int*)d_in[2];
    const int*   label_lens = (const int*)d_in[3];
    float*       out        = (float*)d_out;

    const int nrows = Bc * Tc * Uc;          // 206848, divisible by 8
    lse_kernel<<<nrows / 8, 256>>>(acts, labels);

    const int smem_bytes = (Tc * Uc + Tc * (Uc - 1)) * (int)sizeof(float);  // 205,824 B
    (void)cudaFuncSetAttribute(dp_kernel, cudaFuncAttributeMaxDynamicSharedMemorySize, smem_bytes);
    dp_kernel<<<Bc, 256, smem_bytes>>>(act_lens, label_lens, out);
}

// round 4
// speedup vs baseline: 1.9612x; 1.9612x over previous
#include <cuda_runtime.h>
#include <math.h>

#define Bc 8
#define Tc 256
#define Uc 101
#define Vc 512
#define NEGF (-1e30f)

// Scratch (no cudaMalloc allowed): blankp (B,T,U), emit (B,T,U-1)
__device__ float g_blank[Bc * Tc * Uc];
__device__ float g_emit[Bc * Tc * (Uc - 1)];

// ---------------------------------------------------------------------------
// Pass 1: per-(b,t,u) log-softmax reduction over V=512. One warp per row,
// 4 x float4 per lane, coalesced. HBM-bound (~61us): at the roofline.
// ---------------------------------------------------------------------------
__global__ __launch_bounds__(256) void lse_kernel(const float* __restrict__ acts,
                                                  const int* __restrict__ labels) {
    const int gwarp = blockIdx.x * 8 + (threadIdx.x >> 5);
    const int lane  = threadIdx.x & 31;

    const int u = gwarp % Uc;
    const int b = gwarp / (Tc * Uc);

    const float4* row = reinterpret_cast<const float4*>(acts) + (size_t)gwarp * (Vc / 4);

    int lab = 0;
    if (u < Uc - 1) lab = __ldg(labels + b * (Uc - 1) + u);

    float v[16];
    float mx = -INFINITY;
#pragma unroll
    for (int j = 0; j < 4; j++) {
        float4 f = row[lane + 32 * j];
        v[4 * j + 0] = f.x; v[4 * j + 1] = f.y;
        v[4 * j + 2] = f.z; v[4 * j + 3] = f.w;
        mx = fmaxf(mx, fmaxf(fmaxf(f.x, f.y), fmaxf(f.z, f.w)));
    }

    // label element lives in lane (lab/4)%32, slot 4*(lab/128)+lab%4
    const int src_lane = (lab >> 2) & 31;
    const int src_slot = 4 * (lab >> 7) + (lab & 3);
    float sel;
    switch (src_slot) {
        case 0: sel = v[0]; break;  case 1: sel = v[1]; break;
        case 2: sel = v[2]; break;  case 3: sel = v[3]; break;
        case 4: sel = v[4]; break;  case 5: sel = v[5]; break;
        case 6: sel = v[6]; break;  case 7: sel = v[7]; break;
        case 8: sel = v[8]; break;  case 9: sel = v[9]; break;
        case 10: sel = v[10]; break; case 11: sel = v[11]; break;
        case 12: sel = v[12]; break; case 13: sel = v[13]; break;
        case 14: sel = v[14]; break; default: sel = v[15]; break;
    }
    const float labval = __shfl_sync(0xffffffffu, sel, src_lane);

#pragma unroll
    for (int o = 16; o; o >>= 1) mx = fmaxf(mx, __shfl_xor_sync(0xffffffffu, mx, o));

    float s = 0.f;
#pragma unroll
    for (int k = 0; k < 16; k++) s += __expf(v[k] - mx);
#pragma unroll
    for (int o = 16; o; o >>= 1) s += __shfl_xor_sync(0xffffffffu, s, o);

    const float lse = mx + __logf(s);

    if (lane == 0) {
        g_blank[gwarp] = v[0] - lse;
        if (u < Uc - 1) {
            const int t = (gwarp / Uc) % Tc;
            g_emit[(b * Tc + t) * (Uc - 1) + u] = labval - lse;
        }
    }
}

// ---------------------------------------------------------------------------
// Pass 2: RNNT alpha DP, anti-diagonal wavefront, single warp per batch.
// Rebuilt for critical-path latency:
//  - logaddexp = hi + __logf(1 + __expf(lo-hi))  (pure MUFU chain, no log1pf)
//  - sB/sE values for diagonal d+1 prefetched (addresses independent of p)
//  - incremental clamped smem indices, no per-iter IMAD chains
//  - loss write behind warp-uniform d==dtar check
// ---------------------------------------------------------------------------
__global__ __launch_bounds__(256) void dp_kernel(const int* __restrict__ act_lens,
                                                 const int* __restrict__ label_lens,
                                                 float* __restrict__ out) {
    extern __shared__ float smem[];
    float* sB = smem;                    // Tc*Uc
    float* sE = smem + Tc * Uc;          // Tc*(Uc-1)

    const int b = blockIdx.x;
    const float* gb = g_blank + (size_t)b * Tc * Uc;
    const float* ge = g_emit + (size_t)b * Tc * (Uc - 1);

    for (int i = threadIdx.x; i < Tc * Uc; i += blockDim.x) sB[i] = gb[i];
    for (int i = threadIdx.x; i < Tc * (Uc - 1); i += blockDim.x) sE[i] = ge[i];
    __syncthreads();

    if (threadIdx.x >= 32) return;
    const int lane = threadIdx.x;
    const int tlen = act_lens[b];
    const int ulen = label_lens[b];
    const int dtar = tlen - 1 + ulen;
    const int u0   = 4 * lane;

    // degenerate case: loss cell on diagonal 0
    if (dtar == 0 && lane == 0) out[b] = -(0.f + sB[0]);

    // diagonal d=0: only cell (0,0) = 0
    float p[4] = {NEGF, NEGF, NEGF, NEGF};
    if (lane == 0) p[0] = 0.f;

    // running smem indices for diagonal d=1:
    //   iB[k] = (t-1)*Uc   + u  = (d-u-1)*Uc    + u      (+= Uc per d)
    //   iE[k] = t*(Uc-1)   +u-1 = (d-u)*(Uc-1)  + u - 1  (+= Uc-1 per d)
    int iB[4], iE[4];
    float Bv[4], Ev[4];
#pragma unroll
    for (int k = 0; k < 4; k++) {
        const int u = u0 + k;
        iB[k] = (1 - u - 1) * Uc + u;
        iE[k] = (1 - u) * (Uc - 1) + u - 1;
        int jB = iB[k]; jB = jB < 0 ? 0 : (jB > Tc * Uc - 1 ? Tc * Uc - 1 : jB);
        int jE = iE[k]; jE = jE < 0 ? 0 : (jE > Tc * (Uc - 1) - 1 ? Tc * (Uc - 1) - 1 : jE);
        Bv[k] = sB[jB];
        Ev[k] = sE[jE];
    }

    const int D = Tc + Uc - 1;               // 356 diagonals
    for (int d = 1; d < D; d++) {
        // prefetch diagonal d+1 (off the dependency chain)
        float Bn[4], En[4];
#pragma unroll
        for (int k = 0; k < 4; k++) {
            iB[k] += Uc;
            iE[k] += Uc - 1;
            int jB = iB[k]; jB = jB < 0 ? 0 : (jB > Tc * Uc - 1 ? Tc * Uc - 1 : jB);
            int jE = iE[k]; jE = jE < 0 ? 0 : (jE > Tc * (Uc - 1) - 1 ? Tc * (Uc - 1) - 1 : jE);
            Bn[k] = sB[jB];
            En[k] = sE[jE];
        }

        const float up = __shfl_up_sync(0xffffffffu, p[3], 1);
        float nv[4];
#pragma unroll
        for (int k = 0; k < 4; k++) {
            const int u = u0 + k;
            const int t = d - u;
            const bool cell_ok = (u <= Uc - 1) && (t >= 0) && (t <= Tc - 1);
            const float pm1 = (k == 0) ? up : p[k - 1];
            const float a  = (t >= 1 && cell_ok) ? p[k] + Bv[k] : NEGF;
            const float bb = (u >= 1 && cell_ok) ? pm1 + Ev[k] : NEGF;
            const float hi = fmaxf(a, bb);
            const float lo = fminf(a, bb);
            float val = hi + __logf(1.f + __expf(lo - hi));
            if (!cell_ok) val = NEGF;
            nv[k] = val;
        }

        if (d == dtar) {                      // warp-uniform
#pragma unroll
            for (int k = 0; k < 4; k++) {
                const int u = u0 + k;
                if (d - u == tlen - 1 && u == ulen)
                    out[b] = -(nv[k] + sB[(tlen - 1) * Uc + ulen]);
            }
        }

#pragma unroll
        for (int k = 0; k < 4; k++) { p[k] = nv[k]; Bv[k] = Bn[k]; Ev[k] = En[k]; }
    }
}

extern "C" void kernel_launch(void* const* d_in, const int* in_sizes, int n_in,
                              void* d_out, int out_size) {
    const float* acts       = (const float*)d_in[0];
    const int*   labels     = (const int*)d_in[1];
    const int*   act_lens   = (const int*)d_in[2];
    const int*   label_lens = (const int*)d_in[3];
    float*       out        = (float*)d_out;

    const int nrows = Bc * Tc * Uc;          // 206848, divisible by 8
    lse_kernel<<<nrows / 8, 256>>>(acts, labels);

    const int smem_bytes = (Tc * Uc + Tc * (Uc - 1)) * (int)sizeof(float);  // 205,824 B
    (void)cudaFuncSetAttribute(dp_kernel, cudaFuncAttributeMaxDynamicSharedMemorySize, smem_bytes);
    dp_kernel<<<Bc, 256, smem_bytes>>>(act_lens, label_lens, out);
}